// round 3
// baseline (speedup 1.0000x reference)
#include <cuda_runtime.h>
#include <math.h>

#define D_MODEL 1024
#define N_HEAD  16
#define D_HEAD  64
#define N_CTX   2048
#define BATCH   2
#define M_TOTAL (BATCH * N_CTX)   /* 4096 rows */

// Scratch (allocation-guard-safe device globals)
__device__ float g_q[(size_t)M_TOTAL * D_MODEL];
__device__ float g_k[(size_t)M_TOTAL * D_MODEL];
__device__ float g_v[(size_t)M_TOTAL * D_MODEL];
__device__ float g_z[(size_t)M_TOTAL * D_MODEL];
__device__ float g_cos[N_CTX * 32];
__device__ float g_sin[N_CTX * 32];

// ---------------------------------------------------------------------------
// RoPE table: accurate fp64 trig of the fp32-rounded angle (matches the
// reference's fp32 outer(t, inv_freq) then cos/sin). Immune to fast-math.
// ---------------------------------------------------------------------------
__global__ void rope_table_kernel()
{
    int j = threadIdx.x;        // 0..31 (frequency index)
    int s = blockIdx.x;         // 0..2047 (position)
    float inv_freq = (float)pow(10000.0, -(double)j / 32.0);
    float a = (float)s * inv_freq;           // fp32 rounding, like reference
    double sd, cd;
    sincos((double)a, &sd, &cd);             // fp64: correct range reduction
    g_cos[s * 32 + j] = (float)cd;
    g_sin[s * 32 + j] = (float)sd;
}

// ---------------------------------------------------------------------------
// NT GEMM: C[m,n] = sum_k A[m,k] * W[n,k]  (+ bias[n]) (+ add[m,n])
// Tiles: BM=BN=64, BK=16, 256 threads, 4x4 per thread.
// ---------------------------------------------------------------------------
template <bool HAS_BIAS, bool HAS_ADD>
__global__ void __launch_bounds__(256)
gemm_nt_kernel(const float* __restrict__ A, const float* __restrict__ W,
               const float* __restrict__ bias, const float* __restrict__ add,
               float* __restrict__ C, int M, int N, int K)
{
    __shared__ float As[16][64];   // [k][m]
    __shared__ float Bs[16][64];   // [k][n]

    const int tid = threadIdx.x;
    const int tx  = tid & 15;        // n sub-tile
    const int ty  = tid >> 4;        // m sub-tile
    const int m0  = blockIdx.y * 64;
    const int n0  = blockIdx.x * 64;

    const int lrow = tid >> 2;       // 0..63
    const int lk4  = (tid & 3) * 4;  // 0,4,8,12

    float acc[4][4] = {};

    for (int kt = 0; kt < K; kt += 16) {
        float4 av = *(const float4*)&A[(size_t)(m0 + lrow) * K + kt + lk4];
        float4 wv = *(const float4*)&W[(size_t)(n0 + lrow) * K + kt + lk4];
        __syncthreads();
        As[lk4 + 0][lrow] = av.x; As[lk4 + 1][lrow] = av.y;
        As[lk4 + 2][lrow] = av.z; As[lk4 + 3][lrow] = av.w;
        Bs[lk4 + 0][lrow] = wv.x; Bs[lk4 + 1][lrow] = wv.y;
        Bs[lk4 + 2][lrow] = wv.z; Bs[lk4 + 3][lrow] = wv.w;
        __syncthreads();

        #pragma unroll
        for (int kk = 0; kk < 16; kk++) {
            float4 a = *(const float4*)&As[kk][ty * 4];
            float4 b = *(const float4*)&Bs[kk][tx * 4];
            acc[0][0] += a.x * b.x; acc[0][1] += a.x * b.y;
            acc[0][2] += a.x * b.z; acc[0][3] += a.x * b.w;
            acc[1][0] += a.y * b.x; acc[1][1] += a.y * b.y;
            acc[1][2] += a.y * b.z; acc[1][3] += a.y * b.w;
            acc[2][0] += a.z * b.x; acc[2][1] += a.z * b.y;
            acc[2][2] += a.z * b.z; acc[2][3] += a.z * b.w;
            acc[3][0] += a.w * b.x; acc[3][1] += a.w * b.y;
            acc[3][2] += a.w * b.z; acc[3][3] += a.w * b.w;
        }
    }

    float4 bv = make_float4(0.f, 0.f, 0.f, 0.f);
    if (HAS_BIAS) bv = *(const float4*)&bias[n0 + tx * 4];

    #pragma unroll
    for (int i = 0; i < 4; i++) {
        int row = m0 + ty * 4 + i;
        float4 o;
        o.x = acc[i][0] + bv.x; o.y = acc[i][1] + bv.y;
        o.z = acc[i][2] + bv.z; o.w = acc[i][3] + bv.w;
        if (HAS_ADD) {
            float4 xv = *(const float4*)&add[(size_t)row * N + n0 + tx * 4];
            o.x += xv.x; o.y += xv.y; o.z += xv.z; o.w += xv.w;
        }
        *(float4*)&C[(size_t)row * N + n0 + tx * 4] = o;
    }
}

// ---------------------------------------------------------------------------
// RMSNorm (per head, Dh=64, eps=FLT_EPSILON) + RoPE (in-place).
// One warp per (b*s, h) row. Lane i owns elements (2i, 2i+1).
// ---------------------------------------------------------------------------
__global__ void __launch_bounds__(256)
norm_rope_kernel(float* __restrict__ buf, const float* __restrict__ norm_w)
{
    int gwarp = (blockIdx.x * blockDim.x + threadIdx.x) >> 5;
    int lane  = threadIdx.x & 31;
    if (gwarp >= M_TOTAL * N_HEAD) return;

    int m = gwarp >> 4;          // 0..4095 (b*S + s)
    int h = gwarp & 15;
    int s = m & (N_CTX - 1);     // position within sequence

    float* p = buf + (size_t)m * D_MODEL + h * D_HEAD;
    float2 x = *(float2*)(p + 2 * lane);

    float ss = x.x * x.x + x.y * x.y;
    #pragma unroll
    for (int off = 16; off > 0; off >>= 1)
        ss += __shfl_xor_sync(0xFFFFFFFFu, ss, off);

    float r = rsqrtf(ss * (1.0f / 64.0f) + 1.1920929e-07f);

    int d0 = 2 * lane, d1 = 2 * lane + 1;
    float xn0 = x.x * r * norm_w[d0];
    float xn1 = x.y * r * norm_w[d1];

    int j0 = d0 & 31, j1 = d1 & 31;
    float c0 = g_cos[s * 32 + j0], s0 = g_sin[s * 32 + j0];
    float c1 = g_cos[s * 32 + j1], s1 = g_sin[s * 32 + j1];

    // out[2i]   = xn[2i]*cos(a0) - xn[2i+1]*sin(a0)
    // out[2i+1] = xn[2i+1]*cos(a1) + xn[2i]*sin(a1)
    float o0 = xn0 * c0 - xn1 * s0;
    float o1 = xn1 * c1 + xn0 * s1;
    *(float2*)(p + 2 * lane) = make_float2(o0, o1);
}

// ---------------------------------------------------------------------------
// Fused quadratic attention (no softmax):
//   z[q,:] = sum_{k<=q} (q.k / 64)^2 * v[k,:]
// One CTA per (query tile of 64, b*h). 256 threads, 4x4 register tiles.
// Shared: Qs [d][q], Ks [d][k] (reused as Ssq [k][q]), Vs [k][d] = 48 KB.
// ---------------------------------------------------------------------------
__global__ void __launch_bounds__(256)
attn_kernel()
{
    __shared__ float Qs[64][64];   // [d][q]
    __shared__ float Ks[64][64];   // [d][k], reused as Ssq[k][q]
    __shared__ float Vs[64][64];   // [k][d]

    const int qt = blockIdx.x;     // 0..31
    const int bh = blockIdx.y;     // 0..31
    const int b  = bh >> 4;
    const int h  = bh & 15;

    const float* Qg = g_q + (size_t)b * N_CTX * D_MODEL + h * D_HEAD;
    const float* Kg = g_k + (size_t)b * N_CTX * D_MODEL + h * D_HEAD;
    const float* Vg = g_v + (size_t)b * N_CTX * D_MODEL + h * D_HEAD;

    const int tid = threadIdx.x;
    const int tx  = tid & 15;
    const int ty  = tid >> 4;

    // Load Q tile transposed: Qs[d][q]
    #pragma unroll
    for (int r = 0; r < 4; r++) {
        int idx = tid + r * 256;       // 0..1023
        int row = idx >> 4;            // 0..63
        int d4  = (idx & 15) * 4;
        float4 v = *(const float4*)&Qg[(size_t)(qt * 64 + row) * D_MODEL + d4];
        Qs[d4 + 0][row] = v.x; Qs[d4 + 1][row] = v.y;
        Qs[d4 + 2][row] = v.z; Qs[d4 + 3][row] = v.w;
    }

    float zacc[4][4] = {};

    for (int kt = 0; kt <= qt; kt++) {
        __syncthreads();  // previous iter done with Ks(Ssq)/Vs; Qs writes drained (kt=0)

        #pragma unroll
        for (int r = 0; r < 4; r++) {
            int idx = tid + r * 256;
            int row = idx >> 4;
            int d4  = (idx & 15) * 4;
            float4 kv = *(const float4*)&Kg[(size_t)(kt * 64 + row) * D_MODEL + d4];
            Ks[d4 + 0][row] = kv.x;
            Ks[d4 + 1][row] = kv.y;
            Ks[d4 + 2][row] = kv.z;
            Ks[d4 + 3][row] = kv.w;
            float4 vv = *(const float4*)&Vg[(size_t)(kt * 64 + row) * D_MODEL + d4];
            *(float4*)&Vs[row][d4] = vv;
        }
        __syncthreads();

        // S tile = Q . K^T (this thread: rows ty*4+i, cols tx*4+j)
        float sacc[4][4] = {};
        #pragma unroll 8
        for (int d = 0; d < 64; d++) {
            float4 qa = *(const float4*)&Qs[d][ty * 4];
            float4 kb = *(const float4*)&Ks[d][tx * 4];
            sacc[0][0] += qa.x * kb.x; sacc[0][1] += qa.x * kb.y;
            sacc[0][2] += qa.x * kb.z; sacc[0][3] += qa.x * kb.w;
            sacc[1][0] += qa.y * kb.x; sacc[1][1] += qa.y * kb.y;
            sacc[1][2] += qa.y * kb.z; sacc[1][3] += qa.y * kb.w;
            sacc[2][0] += qa.z * kb.x; sacc[2][1] += qa.z * kb.y;
            sacc[2][2] += qa.z * kb.z; sacc[2][3] += qa.z * kb.w;
            sacc[3][0] += qa.w * kb.x; sacc[3][1] += qa.w * kb.y;
            sacc[3][2] += qa.w * kb.z; sacc[3][3] += qa.w * kb.w;
        }
        __syncthreads();  // everyone done reading Ks

        // pattern = (S/64)^2 * causal ; stage into Ks as Ssq[k][q]
        #pragma unroll
        for (int i = 0; i < 4; i++) {
            int qg = qt * 64 + ty * 4 + i;
            #pragma unroll
            for (int j = 0; j < 4; j++) {
                int kg = kt * 64 + tx * 4 + j;
                float p = sacc[i][j] * (1.0f / 64.0f);
                p = p * p;
                if (kg > qg) p = 0.0f;
                Ks[tx * 4 + j][ty * 4 + i] = p;
            }
        }
        __syncthreads();

        // Z += Ssq^T-view @ V  (zacc rows=q, cols=d)
        #pragma unroll 8
        for (int kk = 0; kk < 64; kk++) {
            float4 sa = *(const float4*)&Ks[kk][ty * 4];
            float4 vb = *(const float4*)&Vs[kk][tx * 4];
            zacc[0][0] += sa.x * vb.x; zacc[0][1] += sa.x * vb.y;
            zacc[0][2] += sa.x * vb.z; zacc[0][3] += sa.x * vb.w;
            zacc[1][0] += sa.y * vb.x; zacc[1][1] += sa.y * vb.y;
            zacc[1][2] += sa.y * vb.z; zacc[1][3] += sa.y * vb.w;
            zacc[2][0] += sa.z * vb.x; zacc[2][1] += sa.z * vb.y;
            zacc[2][2] += sa.z * vb.z; zacc[2][3] += sa.z * vb.w;
            zacc[3][0] += sa.w * vb.x; zacc[3][1] += sa.w * vb.y;
            zacc[3][2] += sa.w * vb.z; zacc[3][3] += sa.w * vb.w;
        }
    }

    float* Zg = g_z + (size_t)b * N_CTX * D_MODEL + h * D_HEAD;
    #pragma unroll
    for (int i = 0; i < 4; i++) {
        float4 o = make_float4(zacc[i][0], zacc[i][1], zacc[i][2], zacc[i][3]);
        *(float4*)&Zg[(size_t)(qt * 64 + ty * 4 + i) * D_MODEL + tx * 4] = o;
    }
}

// ---------------------------------------------------------------------------
// Launch
// ---------------------------------------------------------------------------
extern "C" void kernel_launch(void* const* d_in, const int* in_sizes, int n_in,
                              void* d_out, int out_size)
{
    const float* x      = (const float*)d_in[0];
    const float* Wq     = (const float*)d_in[1];
    const float* bq     = (const float*)d_in[2];
    const float* Wk     = (const float*)d_in[3];
    const float* bk     = (const float*)d_in[4];
    const float* Wv     = (const float*)d_in[5];
    const float* bv     = (const float*)d_in[6];
    const float* Wo     = (const float*)d_in[7];
    const float* norm_w = (const float*)d_in[8];
    float* out          = (float*)d_out;

    float *q, *k, *v, *z;
    cudaGetSymbolAddress((void**)&q, g_q);
    cudaGetSymbolAddress((void**)&k, g_k);
    cudaGetSymbolAddress((void**)&v, g_v);
    cudaGetSymbolAddress((void**)&z, g_z);

    dim3 gdim(D_MODEL / 64, M_TOTAL / 64);  // (16, 64)
    dim3 bdim(256);

    // RoPE cos/sin table (fp64 trig, fast-math-proof)
    rope_table_kernel<<<N_CTX, 32>>>();

    // QKV projections with bias
    gemm_nt_kernel<true, false><<<gdim, bdim>>>(x, Wq, bq, nullptr, q,
                                                M_TOTAL, D_MODEL, D_MODEL);
    gemm_nt_kernel<true, false><<<gdim, bdim>>>(x, Wk, bk, nullptr, k,
                                                M_TOTAL, D_MODEL, D_MODEL);
    gemm_nt_kernel<true, false><<<gdim, bdim>>>(x, Wv, bv, nullptr, v,
                                                M_TOTAL, D_MODEL, D_MODEL);

    // RMSNorm + RoPE on q and k (in-place)
    int nwarps = M_TOTAL * N_HEAD;                 // 65536
    int nblocks = nwarps / 8;                      // 256 threads = 8 warps
    norm_rope_kernel<<<nblocks, 256>>>(q, norm_w);
    norm_rope_kernel<<<nblocks, 256>>>(k, norm_w);

    // Fused quadratic attention -> z
    attn_kernel<<<dim3(N_CTX / 64, BATCH * N_HEAD), 256>>>();

    // out = x + z @ Wo^T
    gemm_nt_kernel<false, true><<<gdim, bdim>>>(z, Wo, nullptr, x, out,
                                                M_TOTAL, D_MODEL, D_MODEL);
}